// round 6
// baseline (speedup 1.0000x reference)
#include <cuda_runtime.h>

#define NCH  10
#define DD   11
#define NW   49
#define NR   50
#define FFD  64
#define SEQ  900
#define SCALE 0.3015113445777636f   // 1/sqrt(11)
#define INV11 0.09090909090909091f

__global__ __launch_bounds__(256, 2)
void pve_kernel(const float* __restrict__ x,
                const float* __restrict__ Wqkv,
                const float* __restrict__ Wo,
                const float* __restrict__ W1,
                const float* __restrict__ W2,
                const float* __restrict__ ln1,
                const float* __restrict__ ln2,
                float* __restrict__ out)
{
    __shared__ float cQKV[33 * 11];
    __shared__ float cWo[11 * 11];
    __shared__ float cW1[FFD * 11];
    __shared__ float cW2t[FFD * 11];        // [f][d]
    __shared__ float cL1[11], cL2[11];
    __shared__ float sW[NW][12];            // raw window rows
    __shared__ float sQ[NR][12];
    __shared__ float sK[NW][13];            // stride 13: conflict-free
    __shared__ float sV[NW][12];
    __shared__ float sR[NR][12];            // final rows
    __shared__ float sScr[8][64];           // per-warp scratch

    const int tid  = threadIdx.x;
    const int wid  = tid >> 5;
    const int lane = tid & 31;
    const int b    = blockIdx.x;
    const int h    = b >> 4;
    const int w    = b & 15;
    const unsigned FULL = 0xffffffffu;

    // ---- weights -> shared ----
    for (int i = tid; i < 33 * 11; i += 256) cQKV[i] = Wqkv[i];
    for (int i = tid; i < 11 * 11; i += 256) cWo[i]  = Wo[i];
    for (int i = tid; i < FFD * 11; i += 256) cW1[i] = W1[i];
    for (int i = tid; i < FFD * 11; i += 256) {
        int f = i / 11, d = i - f * 11;
        cW2t[i] = W2[d * FFD + f];
    }
    if (tid < 11) { cL1[tid] = ln1[tid]; cL2[tid] = ln2[tid]; }

    // ---- build the 49 window token vectors ----
    for (int i = tid; i < NW * DD; i += 256) {
        int widx = i / DD, c = i - widx * DD;
        int r = widx / 7, cc = widx - r * 7;
        int iy = h + r - 3, ix = w + cc - 3;
        bool in_img = (iy >= 0) && (iy < 16) && (ix >= 0) && (ix < 16);
        float v;
        if (c < NCH) v = in_img ? x[c * 256 + iy * 16 + ix] : 0.f;
        else         v = in_img ? 0.f : 1.f;
        sW[widx][c] = v;
    }
    __syncthreads();

    // ---- QKV projection (block-wide) + zero query row ----
    for (int i = tid; i < NW * 33 + DD; i += 256) {
        if (i < NW * 33) {
            int widx = i / 33, d = i - widx * 33;
            const float* wr = &cQKV[d * 11];
            float acc = 0.f;
            #pragma unroll
            for (int e = 0; e < 11; e++) acc += sW[widx][e] * wr[e];
            if (d < 11)      sQ[widx][d]      = acc;
            else if (d < 22) sK[widx][d - 11] = acc;
            else             sV[widx][d - 22] = acc;
        } else {
            sQ[NR - 1][i - NW * 33] = 0.f;
        }
    }
    __syncthreads();

    // ==== warp-autonomous per-row pipeline: no block barriers ====
    float* scr = sScr[wid];
    for (int qi = wid; qi < NR; qi += 8) {
        // -- scores: lane handles keys lane and lane+32 --
        const int k1 = lane + 32;
        const bool v1 = (k1 < NW);
        float s0 = 0.f, s1 = 0.f;
        #pragma unroll
        for (int e = 0; e < 11; e++) {
            float qe = sQ[qi][e];
            s0 += qe * sK[lane][e];
            s1 += qe * sK[v1 ? k1 : 0][e];
        }
        s0 *= SCALE;
        s1 = v1 ? s1 * SCALE : -1e30f;

        float m = fmaxf(fmaxf(s0, s1), 0.f);
        #pragma unroll
        for (int o = 16; o; o >>= 1) m = fmaxf(m, __shfl_xor_sync(FULL, m, o));

        float e0 = __expf(s0 - m);
        float e1 = v1 ? __expf(s1 - m) : 0.f;
        float sum = e0 + e1;
        #pragma unroll
        for (int o = 16; o; o >>= 1) sum += __shfl_xor_sync(FULL, sum, o);
        float inv = 1.f / (sum + 851.f * __expf(-m));

        scr[lane] = e0;
        if (v1) scr[k1] = e1;
        __syncwarp();

        // -- sa = attn @ V (lanes 0..10) --
        float sa = 0.f;
        if (lane < 11) {
            #pragma unroll 7
            for (int j = 0; j < NW; j++) sa += scr[j] * sV[j][lane];
            sa *= inv;
        }
        __syncwarp();
        if (lane < 11) scr[lane] = sa;
        __syncwarp();

        // -- out-proj + residual --
        float r = 0.f;
        if (lane < 11) {
            const float* wr = &cWo[lane * 11];
            float o = 0.f;
            #pragma unroll
            for (int e = 0; e < 11; e++) o += scr[e] * wr[e];
            r = ((qi < NW) ? sW[qi][lane] : 0.f) + o;
        }
        __syncwarp();
        if (lane < 11) scr[lane] = r;
        __syncwarp();

        // -- LayerNorm 1 --
        float u = 0.f;
        if (lane < 11) {
            float mu = 0.f;
            #pragma unroll
            for (int e = 0; e < 11; e++) mu += scr[e];
            mu *= INV11;
            float var = 0.f;
            #pragma unroll
            for (int e = 0; e < 11; e++) { float t = scr[e] - mu; var += t * t; }
            u = (r - mu) * rsqrtf(var * INV11 + 1e-5f) * cL1[lane];
        }
        __syncwarp();
        if (lane < 11) scr[lane] = u;
        __syncwarp();

        // -- FF hidden: lane computes f=lane, f=lane+32 --
        float h0 = 0.f, h1 = 0.f;
        {
            const float* w0 = &cW1[lane * 11];
            const float* w1p = &cW1[(lane + 32) * 11];
            #pragma unroll
            for (int e = 0; e < 11; e++) {
                float ue = scr[e];
                h0 += ue * w0[e];
                h1 += ue * w1p[e];
            }
            h0 = fmaxf(h0, 0.f);
            h1 = fmaxf(h1, 0.f);
        }
        __syncwarp();
        scr[lane]      = h0;
        scr[lane + 32] = h1;
        __syncwarp();

        // -- FF out + residual --
        float r2 = 0.f;
        if (lane < 11) {
            float acc = 0.f;
            #pragma unroll 8
            for (int f = 0; f < FFD; f++) acc += scr[f] * cW2t[f * 11 + lane];
            r2 = u + acc;
        }
        __syncwarp();
        if (lane < 11) scr[lane] = r2;
        __syncwarp();

        // -- LayerNorm 2 -> sR --
        if (lane < 11) {
            float mu = 0.f;
            #pragma unroll
            for (int e = 0; e < 11; e++) mu += scr[e];
            mu *= INV11;
            float var = 0.f;
            #pragma unroll
            for (int e = 0; e < 11; e++) { float t = scr[e] - mu; var += t * t; }
            sR[qi][lane] = (r2 - mu) * rsqrtf(var * INV11 + 1e-5f) * cL2[lane];
        }
        __syncwarp();
    }
    __syncthreads();

    // ---- coalesced output write [b, c, s] ----
    float* ob = out + (size_t)b * (NCH * SEQ);
    for (int i = tid; i < NCH * SEQ; i += 256) {
        int c = i / SEQ, s = i - c * SEQ;
        int r = s / 30, cc = s - r * 30;
        float v = (r < 7 && cc < 7) ? sR[r * 7 + cc][c] : sR[NR - 1][c];
        ob[i] = v;
    }
}

extern "C" void kernel_launch(void* const* d_in, const int* in_sizes, int n_in,
                              void* d_out, int out_size)
{
    const float* x    = (const float*)d_in[0];
    const float* Wqkv = (const float*)d_in[1];
    const float* Wo   = (const float*)d_in[2];
    const float* W1   = (const float*)d_in[3];
    const float* W2   = (const float*)d_in[4];
    const float* ln1  = (const float*)d_in[5];
    const float* ln2  = (const float*)d_in[6];
    float* out = (float*)d_out;

    pve_kernel<<<256, 256>>>(x, Wqkv, Wo, W1, W2, ln1, ln2, out);
}